// round 2
// baseline (speedup 1.0000x reference)
#include <cuda_runtime.h>
#include <math.h>

#define DIMC 512
#define HC 8
#define HDC 64
#define BC 2
#define SC 512
#define BHC 16
#define EPSC 1e-5f

// ---------------- scratch (device globals; no allocation allowed) ----------------
__device__ float g_qkv[BC * SC * 3 * DIMC];   // [1024][1536]
__device__ float g_W  [BHC * SC * SC];        // [16][512][512]
__device__ float g_X0 [BHC * SC * SC];
__device__ float g_X1 [BHC * SC * SC];
__device__ float g_Y  [BHC * SC * SC];
__device__ float g_ctx [BHC * SC * HDC];      // [16][512][64]
__device__ float g_ctx2[BHC * SC * HDC];
__device__ float g_ga [BC * SC * DIMC];       // [1024][512] (b,s,h*64+d)
__device__ float g_scale[BHC];
__device__ float g_mu  [HC * SC];
__device__ float g_rstd[HC * SC];

// ---------------- big SGEMM: 128x128 tile, BK=8, 256 threads, 8x8 micro ----------
// BMODE: 0 = NN (B[k*ldb+n]), 1 = NT (B[n*ldb+k]), 2 = NN with (2I - B)
template<int BMODE, bool BIAS>
__global__ __launch_bounds__(256) void sgemm128(
    const float* __restrict__ Ag, const float* __restrict__ Bg,
    float* __restrict__ Cg, const float* __restrict__ bias,
    int M, int N, int K, int lda, int ldb, int ldc,
    long aB, long bB, long cB)
{
    const float* A = Ag + (long)blockIdx.z * aB;
    const float* B = Bg + (long)blockIdx.z * bB;
    float*       C = Cg + (long)blockIdx.z * cB;
    const int m0 = blockIdx.y * 128;
    const int n0 = blockIdx.x * 128;
    const int t  = threadIdx.x;

    __shared__ float As[8][128];
    __shared__ float Bs[8][128];

    const int ty = t >> 4, tx = t & 15;

    float acc[8][8];
#pragma unroll
    for (int i = 0; i < 8; i++)
#pragma unroll
        for (int j = 0; j < 8; j++) acc[i][j] = 0.f;

    const int arow = t >> 1;        // 0..127
    const int acol = (t & 1) * 4;   // 0 or 4

    for (int k0 = 0; k0 < K; k0 += 8) {
        // load A tile 128x8 (store transposed As[k][m])
        {
            float4 v = *(const float4*)&A[(long)(m0 + arow) * lda + k0 + acol];
            As[acol + 0][arow] = v.x;
            As[acol + 1][arow] = v.y;
            As[acol + 2][arow] = v.z;
            As[acol + 3][arow] = v.w;
        }
        // load B tile 8x128
        if (BMODE == 1) {
            const int nrow = t >> 1, ncol = (t & 1) * 4;
            float4 v = *(const float4*)&B[(long)(n0 + nrow) * ldb + k0 + ncol];
            Bs[ncol + 0][nrow] = v.x;
            Bs[ncol + 1][nrow] = v.y;
            Bs[ncol + 2][nrow] = v.z;
            Bs[ncol + 3][nrow] = v.w;
        } else {
            const int brow = t >> 5, bcol = (t & 31) * 4;
            float4 v = *(const float4*)&B[(long)(k0 + brow) * ldb + n0 + bcol];
            if (BMODE == 2) {
                const int kg = k0 + brow, ng = n0 + bcol;
                v.x = (kg == ng + 0) ? 2.f - v.x : -v.x;
                v.y = (kg == ng + 1) ? 2.f - v.y : -v.y;
                v.z = (kg == ng + 2) ? 2.f - v.z : -v.z;
                v.w = (kg == ng + 3) ? 2.f - v.w : -v.w;
            }
            *(float4*)&Bs[brow][bcol] = v;
        }
        __syncthreads();

#pragma unroll
        for (int kk = 0; kk < 8; kk++) {
            float a[8], b[8];
            *(float4*)&a[0] = *(const float4*)&As[kk][ty * 4];
            *(float4*)&a[4] = *(const float4*)&As[kk][64 + ty * 4];
            *(float4*)&b[0] = *(const float4*)&Bs[kk][tx * 4];
            *(float4*)&b[4] = *(const float4*)&Bs[kk][64 + tx * 4];
#pragma unroll
            for (int i = 0; i < 8; i++)
#pragma unroll
                for (int j = 0; j < 8; j++)
                    acc[i][j] = fmaf(a[i], b[j], acc[i][j]);
        }
        __syncthreads();
    }

#pragma unroll
    for (int i = 0; i < 8; i++) {
        const int m = m0 + ((i < 4) ? (ty * 4 + i) : (64 + ty * 4 + i - 4));
#pragma unroll
        for (int j = 0; j < 8; j++) {
            const int n = n0 + ((j < 4) ? (tx * 4 + j) : (64 + tx * 4 + j - 4));
            float v = acc[i][j];
            if (BIAS) v += bias[n];
            C[(long)m * ldc + n] = v;
        }
    }
}

// ---------------- small-N SGEMM: 64(M)x64(N) tile, BK=16, 256 threads, 4x4 ------
// batch offset = (z>>3)*Outer + (z&7)*Inner for each of A, B, C
template<int TRANSA, int ANORM>
__global__ __launch_bounds__(256) void sgemm_n64(
    const float* __restrict__ Ag, const float* __restrict__ Bg, float* __restrict__ Cg,
    int K, int lda, int ldb, int ldc,
    long aO, long aI, long bO, long bI, long cO, long cI)
{
    const int z = blockIdx.z;
    const float* A = Ag + (long)(z >> 3) * aO + (long)(z & 7) * aI;
    const float* B = Bg + (long)(z >> 3) * bO + (long)(z & 7) * bI;
    float*       C = Cg + (long)(z >> 3) * cO + (long)(z & 7) * cI;
    const float* mu   = g_mu   + (z & 7) * SC;
    const float* rstd = g_rstd + (z & 7) * SC;

    const int m0 = blockIdx.x * 64;
    const int t  = threadIdx.x;
    const int ty = t >> 4, tx = t & 15;

    __shared__ float As[16][64];
    __shared__ float Bs[16][64];

    float acc[4][4];
#pragma unroll
    for (int i = 0; i < 4; i++)
#pragma unroll
        for (int j = 0; j < 4; j++) acc[i][j] = 0.f;

    for (int k0 = 0; k0 < K; k0 += 16) {
        if (TRANSA) {
            const int kr = t >> 4, mc = (t & 15) * 4;
            *(float4*)&As[kr][mc] = *(const float4*)&A[(long)(k0 + kr) * lda + m0 + mc];
        } else {
            const int ar = t >> 2, ac = (t & 3) * 4;
            float4 v = *(const float4*)&A[(long)(m0 + ar) * lda + k0 + ac];
            if (ANORM) {
                v.x = (v.x - mu[k0 + ac + 0]) * rstd[k0 + ac + 0];
                v.y = (v.y - mu[k0 + ac + 1]) * rstd[k0 + ac + 1];
                v.z = (v.z - mu[k0 + ac + 2]) * rstd[k0 + ac + 2];
                v.w = (v.w - mu[k0 + ac + 3]) * rstd[k0 + ac + 3];
            }
            As[ac + 0][ar] = v.x;
            As[ac + 1][ar] = v.y;
            As[ac + 2][ar] = v.z;
            As[ac + 3][ar] = v.w;
        }
        {
            const int kr = t >> 4, nc = (t & 15) * 4;
            *(float4*)&Bs[kr][nc] = *(const float4*)&B[(long)(k0 + kr) * ldb + nc];
        }
        __syncthreads();
#pragma unroll
        for (int kk = 0; kk < 16; kk++) {
            float a[4], b[4];
            *(float4*)a = *(const float4*)&As[kk][ty * 4];
            *(float4*)b = *(const float4*)&Bs[kk][tx * 4];
#pragma unroll
            for (int i = 0; i < 4; i++)
#pragma unroll
                for (int j = 0; j < 4; j++)
                    acc[i][j] = fmaf(a[i], b[j], acc[i][j]);
        }
        __syncthreads();
    }

#pragma unroll
    for (int i = 0; i < 4; i++)
#pragma unroll
        for (int j = 0; j < 4; j++)
            C[(long)(m0 + ty * 4 + i) * ldc + tx * 4 + j] = acc[i][j];
}

// ---------------- Laplacian kernel tile: W[i,j] = tril * exp(-L1(q_i,k_j)/4) ----
__global__ __launch_bounds__(1024) void laplacian_kernel()
{
    const int z = blockIdx.z;                 // bh
    const int b = z >> 3, h = z & 7;
    const int i0 = blockIdx.y * 32, j0 = blockIdx.x * 32;
    const int tx = threadIdx.x, ty = threadIdx.y;
    const int tid = ty * 32 + tx;

    float* Wp = g_W + (long)z * SC * SC;

    if (j0 > i0 + 31) {   // fully masked tile
        Wp[(long)(i0 + ty) * SC + j0 + tx] = 0.f;
        return;
    }

    const float* qp = g_qkv + (long)b * SC * 3 * DIMC + h * HDC;            // q
    const float* kp = g_qkv + (long)b * SC * 3 * DIMC + DIMC + h * HDC;     // k

    __shared__ float qs[32][65];
    __shared__ float ks[32][65];

    for (int idx = tid; idx < 2048; idx += 1024) {
        const int r = idx >> 6, d = idx & 63;
        qs[r][d] = qp[(long)(i0 + r) * (3 * DIMC) + d];
        ks[r][d] = kp[(long)(j0 + r) * (3 * DIMC) + d];
    }
    __syncthreads();

    const int i = i0 + ty, j = j0 + tx;
    float out = 0.f;
    if (j <= i) {
        float s = 0.f;
#pragma unroll
        for (int d = 0; d < 64; d++)
            s += fabsf(qs[ty][d] - ks[tx][d]);
        out = expf(-0.25f * s);
    }
    Wp[(long)i * SC + j] = out;
}

// ---------------- NS init scale: 1/(max colsum * max rowsum) --------------------
__global__ __launch_bounds__(512) void ns_scale_kernel()
{
    const int z = blockIdx.x;
    const float* W = g_W + (long)z * SC * SC;
    const int t = threadIdx.x;

    float cs = 0.f, rs = 0.f;
    for (int i = 0; i < SC; i++) cs += W[(long)i * SC + t];
    for (int j = 0; j < SC; j++) rs += W[(long)t * SC + j];

    __shared__ float red[512];
    __shared__ float n1s;
    red[t] = cs; __syncthreads();
    for (int s = 256; s > 0; s >>= 1) {
        if (t < s) red[t] = fmaxf(red[t], red[t + s]);
        __syncthreads();
    }
    if (t == 0) n1s = red[0];
    __syncthreads();
    red[t] = rs; __syncthreads();
    for (int s = 256; s > 0; s >>= 1) {
        if (t < s) red[t] = fmaxf(red[t], red[t + s]);
        __syncthreads();
    }
    if (t == 0) g_scale[z] = 1.f / (n1s * red[0]);
}

// ---------------- X0 = W^T * scale ----------------------------------------------
__global__ __launch_bounds__(256) void transpose_scale_kernel()
{
    const int z = blockIdx.z;
    const float s = g_scale[z];
    const float* in = g_W + (long)z * SC * SC;
    float* out = g_X0 + (long)z * SC * SC;
    const int x0 = blockIdx.x * 32, y0 = blockIdx.y * 32;
    const int tx = threadIdx.x, ty = threadIdx.y;   // 32 x 8

    __shared__ float tile[32][33];
    for (int r = ty; r < 32; r += 8)
        tile[r][tx] = in[(long)(y0 + r) * SC + x0 + tx];
    __syncthreads();
    for (int r = ty; r < 32; r += 8)
        out[(long)(x0 + r) * SC + y0 + tx] = tile[tx][r] * s;
}

// ---------------- whitening stats per (h, key column j) -------------------------
__global__ __launch_bounds__(512) void stats_kernel()
{
    const int h = blockIdx.x, j = threadIdx.x;
    float s = 0.f, s2 = 0.f;
    for (int b = 0; b < BC; b++) {
        const float* Wp = g_W + (long)(b * HC + h) * SC * SC + j;
        for (int i = 0; i < SC; i++) {
            const float v = Wp[(long)i * SC];
            s += v; s2 += v * v;
        }
    }
    const float n = (float)(BC * SC);
    const float m = s / n;
    const float var = (s2 - n * m * m) / (n - 1.f);
    g_mu[h * SC + j]   = m;
    g_rstd[h * SC + j] = rsqrtf(var + EPSC);
}

// ---------------- launch --------------------------------------------------------
extern "C" void kernel_launch(void* const* d_in, const int* in_sizes, int n_in,
                              void* d_out, int out_size)
{
    (void)in_sizes; (void)n_in; (void)out_size;
    const float* x      = (const float*)d_in[0];
    const float* qkv_w  = (const float*)d_in[1];
    const float* qkv_b  = (const float*)d_in[2];
    const float* proj_w = (const float*)d_in[3];
    const float* proj_b = (const float*)d_in[4];
    float* out = (float*)d_out;

    static float *pQKV = nullptr, *pW, *pX0, *pX1, *pY, *pCTX, *pCTX2, *pGA;
    if (!pQKV) {
        cudaGetSymbolAddress((void**)&pQKV, g_qkv);
        cudaGetSymbolAddress((void**)&pW,   g_W);
        cudaGetSymbolAddress((void**)&pX0,  g_X0);
        cudaGetSymbolAddress((void**)&pX1,  g_X1);
        cudaGetSymbolAddress((void**)&pY,   g_Y);
        cudaGetSymbolAddress((void**)&pCTX, g_ctx);
        cudaGetSymbolAddress((void**)&pCTX2,g_ctx2);
        cudaGetSymbolAddress((void**)&pGA,  g_ga);
    }

    const long MS = (long)SC * SC;        // 262144
    const long CS = (long)SC * HDC;       // 32768

    // 1) qkv = x @ qkv_w^T + qkv_b   [1024 x 1536]
    sgemm128<1, true><<<dim3(12, 8, 1), 256>>>(
        x, qkv_w, pQKV, qkv_b, 1024, 1536, 512, 512, 512, 1536, 0, 0, 0);

    // 2) W = tril(exp(-L1(q,k)/4))
    laplacian_kernel<<<dim3(16, 16, 16), dim3(32, 32)>>>();

    // 3) scale = 1/(n1*ninf);  4) X0 = W^T * scale
    ns_scale_kernel<<<16, 512>>>();
    transpose_scale_kernel<<<dim3(16, 16, 16), dim3(32, 8)>>>();

    // 5) Newton-Schulz: X <- X (2I - A X), 5 iterations
    float* cur = pX0; float* nxt = pX1;
    for (int it = 0; it < 5; it++) {
        sgemm128<0, false><<<dim3(4, 4, 16), 256>>>(
            pW, cur, pY, nullptr, 512, 512, 512, 512, 512, 512, MS, MS, MS);
        sgemm128<2, false><<<dim3(4, 4, 16), 256>>>(
            cur, pY, nxt, nullptr, 512, 512, 512, 512, 512, 512, MS, MS, MS);
        float* tmp = cur; cur = nxt; nxt = tmp;
    }

    // 6) whitening stats
    stats_kernel<<<8, 512>>>();

    // 7) ctx = W^T @ v
    sgemm_n64<1, 0><<<dim3(8, 1, 16), 256>>>(
        pW, pQKV + 2 * DIMC, pCTX, 512, 512, 3 * DIMC, HDC,
        8 * MS, MS, (long)SC * 3 * DIMC, HDC, 8 * CS, CS);

    // 8) ctx2 = W_inv @ ctx
    sgemm_n64<0, 0><<<dim3(8, 1, 16), 256>>>(
        cur, pCTX, pCTX2, 512, 512, HDC, HDC,
        8 * MS, MS, 8 * CS, CS, 8 * CS, CS);

    // 9) ga = W_norm @ ctx2, written to [b, s, h*64+d] layout
    sgemm_n64<0, 1><<<dim3(8, 1, 16), 256>>>(
        pW, pCTX2, pGA, 512, 512, HDC, 512,
        8 * MS, MS, 8 * CS, CS, MS, HDC);

    // 10) out = ga @ proj_w^T + proj_b   [1024 x 512]
    sgemm128<1, true><<<dim3(4, 8, 1), 256>>>(
        pGA, proj_w, out, proj_b, 1024, 512, 512, 512, 512, 512, 0, 0, 0);
}

// round 5
// speedup vs baseline: 1.4974x; 1.4974x over previous
#include <cuda_runtime.h>
#include <math.h>
#include <stdint.h>

#define DIMC 512
#define HC 8
#define HDC 64
#define BC 2
#define SC 512
#define BHC 16
#define EPSC 1e-5f

// ---------------- scratch (device globals; no allocation allowed) ----------------
__device__ float g_qkv[BC * SC * 3 * DIMC];   // [1024][1536]
__device__ float g_W  [BHC * SC * SC];        // [16][512][512]
__device__ float g_X0 [BHC * SC * SC];
__device__ float g_X1 [BHC * SC * SC];
__device__ float g_Y  [BHC * SC * SC];
__device__ float g_ctx [BHC * SC * HDC];
__device__ float g_ctx2[BHC * SC * HDC];
__device__ float g_ga [BC * SC * DIMC];
__device__ float g_scale[BHC];
__device__ float g_mu  [HC * SC];
__device__ float g_rstd[HC * SC];

// ============================ helpers ============================================
__device__ __forceinline__ uint32_t smem_to_u32(const void* p) {
    uint32_t a;
    asm("{ .reg .u64 t; cvta.to.shared.u64 t, %1; cvt.u32.u64 %0, t; }" : "=r"(a) : "l"(p));
    return a;
}
__device__ __forceinline__ void cpa16(uint32_t dst, const float* src) {
    asm volatile("cp.async.cg.shared.global [%0], [%1], 16;" :: "r"(dst), "l"(src));
}
__device__ __forceinline__ void cpa_commit() {
    asm volatile("cp.async.commit_group;" ::: "memory");
}
__device__ __forceinline__ uint2 tf32_split(float v) {
    uint32_t h, l;
    asm("cvt.rna.tf32.f32 %0, %1;" : "=r"(h) : "f"(v));
    float r = v - __uint_as_float(h);
    asm("cvt.rna.tf32.f32 %0, %1;" : "=r"(l) : "f"(r));
    return make_uint2(h, l);
}
__device__ __forceinline__ void mma8(float d[4], const uint32_t a[4],
                                     uint32_t b0, uint32_t b1) {
    asm volatile(
        "mma.sync.aligned.m16n8k8.row.col.f32.tf32.tf32.f32 "
        "{%0,%1,%2,%3}, {%4,%5,%6,%7}, {%8,%9}, {%0,%1,%2,%3};"
        : "+f"(d[0]), "+f"(d[1]), "+f"(d[2]), "+f"(d[3])
        : "r"(a[0]), "r"(a[1]), "r"(a[2]), "r"(a[3]), "r"(b0), "r"(b1));
}

// ======================= tensor-core 3xTF32 GEMM (mma.sync) ======================
// C[M,N] = op_A(A) @ op_B(B) [+ bias].  CTA tile 128x128, K=512 (16 kb of 32),
// 256 threads = 8 warps, warp tile 32(m) x 64(n), mma m16n8k8 tf32, 3x split.
// AMODE: 0 plain, 1 -> A' = 2I - A (diag by GLOBAL indices)
// BMODE: 1 = NT (B row-major [n][k]), 0 = NN (B row-major [k][n])
// ASCALE/BSCALE: multiply operand by g_scale[blockIdx.z]
#define MM_ABUF 18432               // 128 x 36 floats
#define MM_BUF  36864               // A + B regions per stage
#define MM_SMEM (2 * MM_BUF)        // double buffered: 73728 B

template<int BMODE>
__device__ __forceinline__ void mm_issue(
    const float* __restrict__ A, const float* __restrict__ B,
    int lda, int ldb, int m0, int n0, int t, int kb, uint32_t sb, int buf)
{
    const int k0 = kb * 32;
    const uint32_t abase = sb + buf * MM_BUF;
    const uint32_t bbase = abase + MM_ABUF;
#pragma unroll
    for (int i = 0; i < 4; i++) {
        const int idx = t + i * 256;
        const int r = idx >> 3, c4 = (idx & 7) * 4;
        cpa16(abase + (uint32_t)(r * 36 + c4) * 4u,
              A + (long)(m0 + r) * lda + k0 + c4);
    }
    if (BMODE == 1) {
#pragma unroll
        for (int i = 0; i < 4; i++) {
            const int idx = t + i * 256;
            const int r = idx >> 3, c4 = (idx & 7) * 4;
            cpa16(bbase + (uint32_t)(r * 36 + c4) * 4u,
                  B + (long)(n0 + r) * ldb + k0 + c4);
        }
    } else {
#pragma unroll
        for (int i = 0; i < 4; i++) {
            const int idx = t + i * 256;
            const int kr = idx >> 5, c4 = (idx & 31) * 4;
            cpa16(bbase + (uint32_t)(kr * 136 + c4) * 4u,
                  B + (long)(k0 + kr) * ldb + n0 + c4);
        }
    }
    cpa_commit();
}

template<int AMODE, int BMODE, int ASCALE, int BSCALE, int BIAS>
__global__ __launch_bounds__(256) void mma_gemm(
    const float* __restrict__ Ag, const float* __restrict__ Bg,
    float* __restrict__ Cg, const float* __restrict__ bias,
    int lda, int ldb, int ldc, long aB, long bB, long cB)
{
    extern __shared__ char dsm[];
    const uint32_t sb = smem_to_u32(dsm);
    const int t = threadIdx.x;
    const int w = t >> 5, lane = t & 31;
    const int tg = lane >> 2, tig = lane & 3;
    const int wm = (w & 3) * 32, wn = (w >> 2) * 64;
    const int m0 = blockIdx.y * 128, n0 = blockIdx.x * 128;
    const float* A = Ag + (long)blockIdx.z * aB;
    const float* B = Bg + (long)blockIdx.z * bB;
    float*       C = Cg + (long)blockIdx.z * cB;
    float s = 1.f;
    if (ASCALE || BSCALE) s = g_scale[blockIdx.z];

    float acc[2][8][4];
#pragma unroll
    for (int i = 0; i < 2; i++)
#pragma unroll
        for (int j = 0; j < 8; j++)
#pragma unroll
            for (int p = 0; p < 4; p++) acc[i][j][p] = 0.f;

    mm_issue<BMODE>(A, B, lda, ldb, m0, n0, t, 0, sb, 0);

    for (int kb = 0; kb < 16; kb++) {
        if (kb < 15) {
            mm_issue<BMODE>(A, B, lda, ldb, m0, n0, t, kb + 1, sb, (kb + 1) & 1);
            asm volatile("cp.async.wait_group 1;" ::: "memory");
        } else {
            asm volatile("cp.async.wait_group 0;" ::: "memory");
        }
        __syncthreads();

        const float* As = (const float*)(dsm + (kb & 1) * MM_BUF);
        const float* Bs = (const float*)(dsm + (kb & 1) * MM_BUF + MM_ABUF);

#pragma unroll
        for (int kk = 0; kk < 4; kk++) {
            const int kc = kk * 8 + tig;
            uint32_t ah[2][4], al[2][4];
#pragma unroll
            for (int mt = 0; mt < 2; mt++) {
                const int ml = wm + 16 * mt + tg;
                float v[4];
                v[0] = As[ml * 36 + kc];
                v[1] = As[(ml + 8) * 36 + kc];
                v[2] = As[ml * 36 + kc + 4];
                v[3] = As[(ml + 8) * 36 + kc + 4];
                if (ASCALE) { v[0] *= s; v[1] *= s; v[2] *= s; v[3] *= s; }
                if (AMODE == 1) {
                    const int mg0 = m0 + ml, mg1 = mg0 + 8;
                    const int kg0 = kb * 32 + kc, kg1 = kg0 + 4;
                    v[0] = (mg0 == kg0) ? 2.f - v[0] : -v[0];
                    v[1] = (mg1 == kg0) ? 2.f - v[1] : -v[1];
                    v[2] = (mg0 == kg1) ? 2.f - v[2] : -v[2];
                    v[3] = (mg1 == kg1) ? 2.f - v[3] : -v[3];
                }
#pragma unroll
                for (int j = 0; j < 4; j++) {
                    const uint2 sp = tf32_split(v[j]);
                    ah[mt][j] = sp.x; al[mt][j] = sp.y;
                }
            }
#pragma unroll
            for (int nt = 0; nt < 8; nt++) {
                const int nl = wn + 8 * nt + tg;
                float vb0, vb1;
                if (BMODE == 1) {
                    vb0 = Bs[nl * 36 + kc];
                    vb1 = Bs[nl * 36 + kc + 4];
                } else {
                    vb0 = Bs[kc * 136 + nl];
                    vb1 = Bs[(kc + 4) * 136 + nl];
                }
                if (BSCALE) { vb0 *= s; vb1 *= s; }
                const uint2 s0 = tf32_split(vb0), s1 = tf32_split(vb1);
#pragma unroll
                for (int mt = 0; mt < 2; mt++) {
                    mma8(acc[mt][nt], ah[mt], s0.x, s1.x);   // Ah*Bh
                    mma8(acc[mt][nt], ah[mt], s0.y, s1.y);   // Ah*Bl
                    mma8(acc[mt][nt], al[mt], s0.x, s1.x);   // Al*Bh
                }
            }
        }
        __syncthreads();
    }

    // epilogue
#pragma unroll
    for (int mt = 0; mt < 2; mt++) {
        const int r0 = m0 + wm + 16 * mt + tg;
#pragma unroll
        for (int nt = 0; nt < 8; nt++) {
            const int c = n0 + wn + 8 * nt + 2 * tig;
            float b0 = 0.f, b1 = 0.f;
            if (BIAS) { b0 = bias[c]; b1 = bias[c + 1]; }
            *(float2*)&C[(long)r0 * ldc + c] =
                make_float2(acc[mt][nt][0] + b0, acc[mt][nt][1] + b1);
            *(float2*)&C[(long)(r0 + 8) * ldc + c] =
                make_float2(acc[mt][nt][2] + b0, acc[mt][nt][3] + b1);
        }
    }
}

// ---------------- small-N SGEMM: 64(M)x64(N) tile, BK=16, 256 threads, 4x4 ------
template<int TRANSA, int ANORM>
__global__ __launch_bounds__(256) void sgemm_n64(
    const float* __restrict__ Ag, const float* __restrict__ Bg, float* __restrict__ Cg,
    int K, int lda, int ldb, int ldc,
    long aO, long aI, long bO, long bI, long cO, long cI)
{
    const int z = blockIdx.z;
    const float* A = Ag + (long)(z >> 3) * aO + (long)(z & 7) * aI;
    const float* B = Bg + (long)(z >> 3) * bO + (long)(z & 7) * bI;
    float*       C = Cg + (long)(z >> 3) * cO + (long)(z & 7) * cI;
    const float* mu   = g_mu   + (z & 7) * SC;
    const float* rstd = g_rstd + (z & 7) * SC;

    const int m0 = blockIdx.x * 64;
    const int t  = threadIdx.x;
    const int ty = t >> 4, tx = t & 15;

    __shared__ float As[16][64];
    __shared__ float Bs[16][64];

    float acc[4][4];
#pragma unroll
    for (int i = 0; i < 4; i++)
#pragma unroll
        for (int j = 0; j < 4; j++) acc[i][j] = 0.f;

    for (int k0 = 0; k0 < K; k0 += 16) {
        if (TRANSA) {
            const int kr = t >> 4, mc = (t & 15) * 4;
            *(float4*)&As[kr][mc] = *(const float4*)&A[(long)(k0 + kr) * lda + m0 + mc];
        } else {
            const int ar = t >> 2, ac = (t & 3) * 4;
            float4 v = *(const float4*)&A[(long)(m0 + ar) * lda + k0 + ac];
            if (ANORM) {
                v.x = (v.x - mu[k0 + ac + 0]) * rstd[k0 + ac + 0];
                v.y = (v.y - mu[k0 + ac + 1]) * rstd[k0 + ac + 1];
                v.z = (v.z - mu[k0 + ac + 2]) * rstd[k0 + ac + 2];
                v.w = (v.w - mu[k0 + ac + 3]) * rstd[k0 + ac + 3];
            }
            As[ac + 0][ar] = v.x;
            As[ac + 1][ar] = v.y;
            As[ac + 2][ar] = v.z;
            As[ac + 3][ar] = v.w;
        }
        {
            const int kr = t >> 4, nc = (t & 15) * 4;
            *(float4*)&Bs[kr][nc] = *(const float4*)&B[(long)(k0 + kr) * ldb + nc];
        }
        __syncthreads();
#pragma unroll
        for (int kk = 0; kk < 16; kk++) {
            float a[4], b[4];
            *(float4*)a = *(const float4*)&As[kk][ty * 4];
            *(float4*)b = *(const float4*)&Bs[kk][tx * 4];
#pragma unroll
            for (int i = 0; i < 4; i++)
#pragma unroll
                for (int j = 0; j < 4; j++)
                    acc[i][j] = fmaf(a[i], b[j], acc[i][j]);
        }
        __syncthreads();
    }

#pragma unroll
    for (int i = 0; i < 4; i++)
#pragma unroll
        for (int j = 0; j < 4; j++)
            C[(long)(m0 + ty * 4 + i) * ldc + tx * 4 + j] = acc[i][j];
}

// ---------------- Laplacian kernel tile: W[i,j] = tril * exp(-L1(q_i,k_j)/4) ----
__global__ __launch_bounds__(1024) void laplacian_kernel()
{
    const int z = blockIdx.z;
    const int b = z >> 3, h = z & 7;
    const int i0 = blockIdx.y * 32, j0 = blockIdx.x * 32;
    const int tx = threadIdx.x, ty = threadIdx.y;
    const int tid = ty * 32 + tx;

    float* Wp = g_W + (long)z * SC * SC;

    if (j0 > i0 + 31) {
        Wp[(long)(i0 + ty) * SC + j0 + tx] = 0.f;
        return;
    }

    const float* qp = g_qkv + (long)b * SC * 3 * DIMC + h * HDC;
    const float* kp = g_qkv + (long)b * SC * 3 * DIMC + DIMC + h * HDC;

    __shared__ float qs[32][65];
    __shared__ float ks[32][65];

    for (int idx = tid; idx < 2048; idx += 1024) {
        const int r = idx >> 6, d = idx & 63;
        qs[r][d] = qp[(long)(i0 + r) * (3 * DIMC) + d];
        ks[r][d] = kp[(long)(j0 + r) * (3 * DIMC) + d];
    }
    __syncthreads();

    const int i = i0 + ty, j = j0 + tx;
    float out = 0.f;
    if (j <= i) {
        float s = 0.f;
#pragma unroll
        for (int d = 0; d < 64; d++)
            s += fabsf(qs[ty][d] - ks[tx][d]);
        out = expf(-0.25f * s);
    }
    Wp[(long)i * SC + j] = out;
}

// ---------------- NS init scale: 1/(max colsum * max rowsum) --------------------
__global__ __launch_bounds__(512) void ns_scale_kernel()
{
    const int z = blockIdx.x;
    const float* W = g_W + (long)z * SC * SC;
    const int t = threadIdx.x;
    const int wid = t >> 5, lid = t & 31;

    float cs = 0.f;
    for (int i = 0; i < SC; i++) cs += W[(long)i * SC + t];

    float rmax = 0.f;
    for (int r = wid; r < SC; r += 16) {
        const float4* row = (const float4*)&W[(long)r * SC];
        float s = 0.f;
#pragma unroll
        for (int p = 0; p < 4; p++) {
            const float4 v = row[lid + p * 32];
            s += v.x + v.y + v.z + v.w;
        }
#pragma unroll
        for (int o = 16; o > 0; o >>= 1) s += __shfl_xor_sync(0xFFFFFFFFu, s, o);
        rmax = fmaxf(rmax, s);
    }

    __shared__ float red[512];
    __shared__ float n1s;
    red[t] = cs; __syncthreads();
    for (int s = 256; s > 0; s >>= 1) {
        if (t < s) red[t] = fmaxf(red[t], red[t + s]);
        __syncthreads();
    }
    if (t == 0) n1s = red[0];
    __syncthreads();
    red[t] = rmax; __syncthreads();
    for (int s = 256; s > 0; s >>= 1) {
        if (t < s) red[t] = fmaxf(red[t], red[t + s]);
        __syncthreads();
    }
    if (t == 0) g_scale[z] = 1.f / (n1s * red[0]);
}

// ---------------- whitening stats per (h, key column j) -------------------------
__global__ __launch_bounds__(256) void stats_kernel()
{
    const int jc = blockIdx.x, h = blockIdx.y;
    const int t = threadIdx.x;
    const int j = jc * 64 + (t & 63);
    const int slice = t >> 6;

    float s = 0.f, s2 = 0.f;
    for (int b = 0; b < BC; b++) {
        const float* Wp = g_W + (long)(b * HC + h) * SC * SC + j;
        for (int i = slice * 128; i < slice * 128 + 128; i++) {
            const float v = Wp[(long)i * SC];
            s += v; s2 += v * v;
        }
    }
    __shared__ float S1[256], S2[256];
    S1[t] = s; S2[t] = s2;
    __syncthreads();
    if (slice == 0) {
        s  = S1[t] + S1[t + 64] + S1[t + 128] + S1[t + 192];
        s2 = S2[t] + S2[t + 64] + S2[t + 128] + S2[t + 192];
        const float n = (float)(BC * SC);
        const float m = s / n;
        const float var = (s2 - n * m * m) / (n - 1.f);
        g_mu[h * SC + j]   = m;
        g_rstd[h * SC + j] = rsqrtf(var + EPSC);
    }
}

// ---------------- launch --------------------------------------------------------
extern "C" void kernel_launch(void* const* d_in, const int* in_sizes, int n_in,
                              void* d_out, int out_size)
{
    (void)in_sizes; (void)n_in; (void)out_size;
    const float* x      = (const float*)d_in[0];
    const float* qkv_w  = (const float*)d_in[1];
    const float* qkv_b  = (const float*)d_in[2];
    const float* proj_w = (const float*)d_in[3];
    const float* proj_b = (const float*)d_in[4];
    float* out = (float*)d_out;

    static float *pQKV = nullptr, *pW, *pX0, *pX1, *pY, *pCTX, *pCTX2, *pGA;
    if (!pQKV) {
        cudaGetSymbolAddress((void**)&pQKV, g_qkv);
        cudaGetSymbolAddress((void**)&pW,   g_W);
        cudaGetSymbolAddress((void**)&pX0,  g_X0);
        cudaGetSymbolAddress((void**)&pX1,  g_X1);
        cudaGetSymbolAddress((void**)&pY,   g_Y);
        cudaGetSymbolAddress((void**)&pCTX, g_ctx);
        cudaGetSymbolAddress((void**)&pCTX2,g_ctx2);
        cudaGetSymbolAddress((void**)&pGA,  g_ga);
        cudaFuncSetAttribute(mma_gemm<0,1,0,0,1>, cudaFuncAttributeMaxDynamicSharedMemorySize, MM_SMEM);
        cudaFuncSetAttribute(mma_gemm<0,1,1,0,0>, cudaFuncAttributeMaxDynamicSharedMemorySize, MM_SMEM);
        cudaFuncSetAttribute(mma_gemm<1,0,0,1,0>, cudaFuncAttributeMaxDynamicSharedMemorySize, MM_SMEM);
        cudaFuncSetAttribute(mma_gemm<0,1,0,0,0>, cudaFuncAttributeMaxDynamicSharedMemorySize, MM_SMEM);
        cudaFuncSetAttribute(mma_gemm<1,0,0,0,0>, cudaFuncAttributeMaxDynamicSharedMemorySize, MM_SMEM);
    }

    const long MS = (long)SC * SC;
    const long CS = (long)SC * HDC;

    // 1) qkv = x @ qkv_w^T + qkv_b   [1024 x 1536]   (NT)
    mma_gemm<0,1,0,0,1><<<dim3(12, 8, 1), 256, MM_SMEM>>>(
        x, qkv_w, pQKV, qkv_b, 512, 512, 1536, 0, 0, 0);

    // 2) W = tril(exp(-L1(q,k)/4))
    laplacian_kernel<<<dim3(16, 16, 16), dim3(32, 32)>>>();

    // 3) scale = 1/(n1*ninf)
    ns_scale_kernel<<<16, 512>>>();

    // 5) Newton-Schulz in TRANSPOSED space: Xt_{k+1} = (2I - Yt) @ Xt,
    //    Yt = Xt @ W^T, with Xt0 = s*W (scale folded into operand loads).
    // iter 0:
    mma_gemm<0,1,1,0,0><<<dim3(4, 4, 16), 256, MM_SMEM>>>(   // Yt0 = (sW) @ W^T
        pW, pW, pY, nullptr, 512, 512, 512, MS, MS, MS);
    mma_gemm<1,0,0,1,0><<<dim3(4, 4, 16), 256, MM_SMEM>>>(   // Xt1 = (2I-Yt0) @ (sW)
        pY, pW, pX0, nullptr, 512, 512, 512, MS, MS, MS);
    float* cur = pX0; float* nxt = pX1;
    for (int it = 1; it < 5; it++) {
        mma_gemm<0,1,0,0,0><<<dim3(4, 4, 16), 256, MM_SMEM>>>(   // Yt = Xt @ W^T
            cur, pW, pY, nullptr, 512, 512, 512, MS, MS, MS);
        mma_gemm<1,0,0,0,0><<<dim3(4, 4, 16), 256, MM_SMEM>>>(   // Xt' = (2I-Yt) @ Xt
            pY, cur, nxt, nullptr, 512, 512, 512, MS, MS, MS);
        float* tmp = cur; cur = nxt; nxt = tmp;
    }
    // cur = Xt5 = (W_inv)^T

    // 6) whitening stats
    stats_kernel<<<dim3(8, 8), 256>>>();

    // 7) ctx = W^T @ v
    sgemm_n64<1, 0><<<dim3(8, 1, 16), 256>>>(
        pW, pQKV + 2 * DIMC, pCTX, 512, 512, 3 * DIMC, HDC,
        8 * MS, MS, (long)SC * 3 * DIMC, HDC, 8 * CS, CS);

    // 8) ctx2 = W_inv @ ctx = (Xt5)^T @ ctx
    sgemm_n64<1, 0><<<dim3(8, 1, 16), 256>>>(
        cur, pCTX, pCTX2, 512, 512, HDC, HDC,
        8 * MS, MS, 8 * CS, CS, 8 * CS, CS);

    // 9) ga = W_norm @ ctx2 -> [b, s, h*64+d]
    sgemm_n64<0, 1><<<dim3(8, 1, 16), 256>>>(
        pW, pCTX2, pGA, 512, 512, HDC, 512,
        8 * MS, MS, 8 * CS, CS, MS, HDC);

    // 10) out = ga @ proj_w^T + proj_b   [1024 x 512]   (NT)
    mma_gemm<0,1,0,0,1><<<dim3(4, 8, 1), 256, MM_SMEM>>>(
        pGA, proj_w, out, proj_b, 512, 512, 512, 0, 0, 0);
}